// round 14
// baseline (speedup 1.0000x reference)
#include <cuda_runtime.h>

#define FULL_MASK 0xffffffffu

constexpr int B_TOT = 131072;
constexpr int DQ = 13;
constexpr int DKV = 32;
constexpr int T_LEN = 24;
constexpr int A_DIM = 32;
constexpr int HD = 8;
constexpr int O_DIM = 32;

constexpr int WARPS_PER_BLOCK = 4;
constexpr int THREADS_PER_BLOCK = WARPS_PER_BLOCK * 32;
constexpr int NUM_BLOCKS = 2048;
constexpr int TOTAL_WARPS = NUM_BLOCKS * WARPS_PER_BLOCK;       // 8192
constexpr int ROWS_PER_WARP = B_TOT / TOTAL_WARPS;              // 16

__device__ __forceinline__ float gelu_exact(float x) {
    // jax.nn.gelu(approximate=False): x * 0.5 * (1 + erf(x / sqrt(2)))
    return 0.5f * x * (1.0f + erff(x * 0.70710678118654752f));
}

__global__ __launch_bounds__(THREADS_PER_BLOCK)
void cross_dmh_attention_kernel(const float* __restrict__ query,
                                const float* __restrict__ kv,
                                const float* __restrict__ Wq,
                                const float* __restrict__ Wk,
                                const float* __restrict__ Wv,
                                const float* __restrict__ Wo,
                                const float* __restrict__ ln_w,
                                const float* __restrict__ ln_b,
                                const float* __restrict__ Wd1,
                                const float* __restrict__ Wd2,
                                float* __restrict__ out)
{
    // ---- shared weights (read conflict-free as [k][lane]) ----
    __shared__ float sWq[DQ * 32];       // Wq[j][a], row-major copy
    __shared__ float sWkT[32 * 32];      // sWkT[a][d] = Wk[d][a]   (transposed)
    __shared__ float sWv[32 * 32];       // Wv[d][a], row-major copy
    __shared__ float sWo[32 * 32];       // Wo[a][o], row-major copy
    __shared__ float sWd1[32 * 32];
    __shared__ float sWd2[32 * 32];
    __shared__ float sLn[64];            // [0:32) weight, [32:64) bias
    // ---- per-warp scratch ----
    __shared__ float  sKv[WARPS_PER_BLOCK][T_LEN * 33];   // kv tile, pad 33
    __shared__ float4 sV4[WARPS_PER_BLOCK][32];           // rT then wT: [d] = {v0,v1,v2,v3}
    __shared__ float4 sAt[WARPS_PER_BLOCK][T_LEN];        // attn[t] = {a0,a1,a2,a3}

    const int tid = threadIdx.x;

    for (int i = tid; i < DQ * 32; i += THREADS_PER_BLOCK) sWq[i] = Wq[i];
    for (int i = tid; i < 1024; i += THREADS_PER_BLOCK) {
        int a = i >> 5;        // target row of sWkT
        int d = i & 31;        // target col of sWkT
        sWkT[i] = Wk[d * 32 + a];
        sWv[i]  = Wv[i];
        sWo[i]  = Wo[i];
        sWd1[i] = Wd1[i];
        sWd2[i] = Wd2[i];
    }
    if (tid < 32) { sLn[tid] = ln_w[tid]; sLn[32 + tid] = ln_b[tid]; }
    __syncthreads();

    const int warp = tid >> 5;
    const int lane = tid & 31;
    const int gw   = blockIdx.x * WARPS_PER_BLOCK + warp;

    float*  kvS = sKv[warp];
    float4* v4  = sV4[warp];
    float*  v4f = (float*)sV4[warp];
    float4* at4 = sAt[warp];

    for (int it = 0; it < ROWS_PER_WARP; ++it) {
        const int row = gw + it * TOTAL_WARPS;

        // ---------- q projection: q[a] = sum_j query[j] * Wq[j][a] ----------
        float qv = (lane < DQ) ? query[row * DQ + lane] : 0.0f;
        float qa = 0.0f;
        #pragma unroll
        for (int j = 0; j < DQ; ++j)
            qa = fmaf(__shfl_sync(FULL_MASK, qv, j), sWq[j * 32 + lane], qa);

        // ---------- r[h][d] = sum_{j<8} Wk[d][h*8+j] * q[h*8+j], scaled ------
        float r0 = 0.f, r1 = 0.f, r2 = 0.f, r3 = 0.f;
        #pragma unroll
        for (int j = 0; j < HD; ++j) {
            r0 = fmaf(__shfl_sync(FULL_MASK, qa, j),      sWkT[(j)      * 32 + lane], r0);
            r1 = fmaf(__shfl_sync(FULL_MASK, qa, 8 + j),  sWkT[(8 + j)  * 32 + lane], r1);
            r2 = fmaf(__shfl_sync(FULL_MASK, qa, 16 + j), sWkT[(16 + j) * 32 + lane], r2);
            r3 = fmaf(__shfl_sync(FULL_MASK, qa, 24 + j), sWkT[(24 + j) * 32 + lane], r3);
        }
        const float iscale = 0.35355339059327373f;   // 1/sqrt(8)
        v4[lane] = make_float4(r0 * iscale, r1 * iscale, r2 * iscale, r3 * iscale);

        // ---------- kv tile: coalesced load, keep column in regs + stage ----
        float kvc[T_LEN];
        const float* kvrow = kv + (size_t)row * (T_LEN * DKV);
        #pragma unroll
        for (int t = 0; t < T_LEN; ++t) {
            float v = kvrow[t * 32 + lane];
            kvc[t] = v;
            kvS[t * 33 + lane] = v;
        }
        __syncwarp();

        // ---------- scores: lane = t, s[h] = kv[t] . r[h] ----------
        const int tl = (lane < T_LEN) ? lane : 0;
        float s0 = 0.f, s1 = 0.f, s2 = 0.f, s3 = 0.f;
        #pragma unroll
        for (int d = 0; d < 32; ++d) {
            float  kd = kvS[tl * 33 + d];
            float4 rr = v4[d];               // broadcast read
            s0 = fmaf(kd, rr.x, s0);
            s1 = fmaf(kd, rr.y, s1);
            s2 = fmaf(kd, rr.z, s2);
            s3 = fmaf(kd, rr.w, s3);
        }
        if (lane >= T_LEN) { s0 = s1 = s2 = s3 = -1e30f; }

        // ---------- softmax over t (cross-lane butterfly) ----------
        float m0 = s0, m1 = s1, m2 = s2, m3 = s3;
        #pragma unroll
        for (int off = 16; off > 0; off >>= 1) {
            m0 = fmaxf(m0, __shfl_xor_sync(FULL_MASK, m0, off));
            m1 = fmaxf(m1, __shfl_xor_sync(FULL_MASK, m1, off));
            m2 = fmaxf(m2, __shfl_xor_sync(FULL_MASK, m2, off));
            m3 = fmaxf(m3, __shfl_xor_sync(FULL_MASK, m3, off));
        }
        float e0 = (lane < T_LEN) ? __expf(s0 - m0) : 0.f;
        float e1 = (lane < T_LEN) ? __expf(s1 - m1) : 0.f;
        float e2 = (lane < T_LEN) ? __expf(s2 - m2) : 0.f;
        float e3 = (lane < T_LEN) ? __expf(s3 - m3) : 0.f;
        float d0 = e0, d1 = e1, d2 = e2, d3 = e3;
        #pragma unroll
        for (int off = 16; off > 0; off >>= 1) {
            d0 += __shfl_xor_sync(FULL_MASK, d0, off);
            d1 += __shfl_xor_sync(FULL_MASK, d1, off);
            d2 += __shfl_xor_sync(FULL_MASK, d2, off);
            d3 += __shfl_xor_sync(FULL_MASK, d3, off);
        }
        float i0 = __fdividef(1.0f, d0);
        float i1 = __fdividef(1.0f, d1);
        float i2 = __fdividef(1.0f, d2);
        float i3 = __fdividef(1.0f, d3);
        if (lane < T_LEN)
            at4[lane] = make_float4(e0 * i0, e1 * i1, e2 * i2, e3 * i3);
        __syncwarp();

        // ---------- weighted kv: w[h][d] = sum_t attn[h][t] * kv[t][d] ------
        float w0 = 0.f, w1 = 0.f, w2 = 0.f, w3 = 0.f;
        #pragma unroll
        for (int t = 0; t < T_LEN; ++t) {
            float4 at = at4[t];              // broadcast read
            float  kd = kvc[t];              // register column
            w0 = fmaf(at.x, kd, w0);
            w1 = fmaf(at.y, kd, w1);
            w2 = fmaf(at.z, kd, w2);
            w3 = fmaf(at.w, kd, w3);
        }
        // safe to overwrite v4: all lanes passed the at-store __syncwarp
        v4[lane] = make_float4(w0, w1, w2, w3);
        __syncwarp();

        // ---------- ctx[a] = sum_d w[h(a)][d] * Wv[d][a] ----------
        const int h = lane >> 3;
        float ctx = 0.f;
        #pragma unroll
        for (int d = 0; d < 32; ++d)
            ctx = fmaf(v4f[d * 4 + h], sWv[d * 32 + lane], ctx);

        // ---------- out[o] = sum_a ctx[a] * Wo[a][o] ----------
        float o1 = 0.f;
        #pragma unroll
        for (int a = 0; a < 32; ++a)
            o1 = fmaf(__shfl_sync(FULL_MASK, ctx, a), sWo[a * 32 + lane], o1);

        // ---------- LayerNorm over 32 ----------
        float sum = o1;
        #pragma unroll
        for (int off = 16; off > 0; off >>= 1)
            sum += __shfl_xor_sync(FULL_MASK, sum, off);
        float mu = sum * 0.03125f;
        float c  = o1 - mu;
        float vv = c * c;
        #pragma unroll
        for (int off = 16; off > 0; off >>= 1)
            vv += __shfl_xor_sync(FULL_MASK, vv, off);
        float var = vv * 0.03125f;
        float y = c * rsqrtf(var + 1e-5f) * sLn[lane] + sLn[32 + lane];

        // ---------- residual GELU MLP ----------
        float g1 = 0.f;
        #pragma unroll
        for (int o = 0; o < 32; ++o)
            g1 = fmaf(__shfl_sync(FULL_MASK, y, o), sWd1[o * 32 + lane], g1);
        float h1 = gelu_exact(g1);

        float g2 = 0.f;
        #pragma unroll
        for (int o = 0; o < 32; ++o)
            g2 = fmaf(__shfl_sync(FULL_MASK, h1, o), sWd2[o * 32 + lane], g2);
        float h2 = gelu_exact(g2);

        out[row * 32 + lane] = y + h2;
        __syncwarp();   // protect v4/at4/kvS for next iteration
    }
}

extern "C" void kernel_launch(void* const* d_in, const int* in_sizes, int n_in,
                              void* d_out, int out_size)
{
    (void)in_sizes; (void)n_in; (void)out_size;
    const float* query = (const float*)d_in[0];
    const float* kv    = (const float*)d_in[1];
    const float* Wq    = (const float*)d_in[2];
    const float* Wk    = (const float*)d_in[3];
    const float* Wv    = (const float*)d_in[4];
    const float* Wo    = (const float*)d_in[5];
    const float* ln_w  = (const float*)d_in[6];
    const float* ln_b  = (const float*)d_in[7];
    const float* Wd1   = (const float*)d_in[8];
    const float* Wd2   = (const float*)d_in[9];
    float* out = (float*)d_out;

    cross_dmh_attention_kernel<<<NUM_BLOCKS, THREADS_PER_BLOCK>>>(
        query, kv, Wq, Wk, Wv, Wo, ln_w, ln_b, Wd1, Wd2, out);
}

// round 15
// speedup vs baseline: 1.0002x; 1.0002x over previous
#include <cuda_runtime.h>

#define FULL_MASK 0xffffffffu

constexpr int B_TOT = 131072;
constexpr int DQ = 13;
constexpr int DKV = 32;
constexpr int T_LEN = 24;
constexpr int A_DIM = 32;
constexpr int HD = 8;
constexpr int O_DIM = 32;

constexpr int WARPS_PER_BLOCK = 4;
constexpr int THREADS_PER_BLOCK = WARPS_PER_BLOCK * 32;
constexpr int NUM_BLOCKS = 2048;
constexpr int TOTAL_WARPS = NUM_BLOCKS * WARPS_PER_BLOCK;       // 8192
constexpr int ROWS_PER_WARP = B_TOT / TOTAL_WARPS;              // 16

__device__ __forceinline__ float gelu_exact(float x) {
    // jax.nn.gelu(approximate=False): x * 0.5 * (1 + erf(x / sqrt(2)))
    return 0.5f * x * (1.0f + erff(x * 0.70710678118654752f));
}

__global__ __launch_bounds__(THREADS_PER_BLOCK)
void cross_dmh_attention_kernel(const float* __restrict__ query,
                                const float* __restrict__ kv,
                                const float* __restrict__ Wq,
                                const float* __restrict__ Wk,
                                const float* __restrict__ Wv,
                                const float* __restrict__ Wo,
                                const float* __restrict__ ln_w,
                                const float* __restrict__ ln_b,
                                const float* __restrict__ Wd1,
                                const float* __restrict__ Wd2,
                                float* __restrict__ out)
{
    // ---- shared weights (read conflict-free as [k][lane]) ----
    __shared__ float sWq[DQ * 32];       // Wq[j][a], row-major copy
    __shared__ float sWkT[32 * 32];      // sWkT[a][d] = Wk[d][a]   (transposed)
    __shared__ float sWv[32 * 32];       // Wv[d][a], row-major copy
    __shared__ float sWo[32 * 32];       // Wo[a][o], row-major copy
    __shared__ float sWd1[32 * 32];
    __shared__ float sWd2[32 * 32];
    __shared__ float sLn[64];            // [0:32) weight, [32:64) bias
    // ---- per-warp scratch ----
    __shared__ float  sKv[WARPS_PER_BLOCK][T_LEN * 33];   // kv tile, pad 33
    __shared__ float4 sV4[WARPS_PER_BLOCK][32];           // rT then wT: [d] = {v0,v1,v2,v3}
    __shared__ float4 sAt[WARPS_PER_BLOCK][T_LEN];        // attn[t] = {a0,a1,a2,a3}

    const int tid = threadIdx.x;

    for (int i = tid; i < DQ * 32; i += THREADS_PER_BLOCK) sWq[i] = Wq[i];
    for (int i = tid; i < 1024; i += THREADS_PER_BLOCK) {
        int a = i >> 5;        // target row of sWkT
        int d = i & 31;        // target col of sWkT
        sWkT[i] = Wk[d * 32 + a];
        sWv[i]  = Wv[i];
        sWo[i]  = Wo[i];
        sWd1[i] = Wd1[i];
        sWd2[i] = Wd2[i];
    }
    if (tid < 32) { sLn[tid] = ln_w[tid]; sLn[32 + tid] = ln_b[tid]; }
    __syncthreads();

    const int warp = tid >> 5;
    const int lane = tid & 31;
    const int gw   = blockIdx.x * WARPS_PER_BLOCK + warp;

    float*  kvS = sKv[warp];
    float4* v4  = sV4[warp];
    float*  v4f = (float*)sV4[warp];
    float4* at4 = sAt[warp];

    for (int it = 0; it < ROWS_PER_WARP; ++it) {
        const int row = gw + it * TOTAL_WARPS;

        // ---------- q projection: q[a] = sum_j query[j] * Wq[j][a] ----------
        float qv = (lane < DQ) ? query[row * DQ + lane] : 0.0f;
        float qa = 0.0f;
        #pragma unroll
        for (int j = 0; j < DQ; ++j)
            qa = fmaf(__shfl_sync(FULL_MASK, qv, j), sWq[j * 32 + lane], qa);

        // ---------- r[h][d] = sum_{j<8} Wk[d][h*8+j] * q[h*8+j], scaled ------
        float r0 = 0.f, r1 = 0.f, r2 = 0.f, r3 = 0.f;
        #pragma unroll
        for (int j = 0; j < HD; ++j) {
            r0 = fmaf(__shfl_sync(FULL_MASK, qa, j),      sWkT[(j)      * 32 + lane], r0);
            r1 = fmaf(__shfl_sync(FULL_MASK, qa, 8 + j),  sWkT[(8 + j)  * 32 + lane], r1);
            r2 = fmaf(__shfl_sync(FULL_MASK, qa, 16 + j), sWkT[(16 + j) * 32 + lane], r2);
            r3 = fmaf(__shfl_sync(FULL_MASK, qa, 24 + j), sWkT[(24 + j) * 32 + lane], r3);
        }
        const float iscale = 0.35355339059327373f;   // 1/sqrt(8)
        v4[lane] = make_float4(r0 * iscale, r1 * iscale, r2 * iscale, r3 * iscale);

        // ---------- kv tile: coalesced load, keep column in regs + stage ----
        float kvc[T_LEN];
        const float* kvrow = kv + (size_t)row * (T_LEN * DKV);
        #pragma unroll
        for (int t = 0; t < T_LEN; ++t) {
            float v = kvrow[t * 32 + lane];
            kvc[t] = v;
            kvS[t * 33 + lane] = v;
        }
        __syncwarp();

        // ---------- scores: lane = t, s[h] = kv[t] . r[h] ----------
        const int tl = (lane < T_LEN) ? lane : 0;
        float s0 = 0.f, s1 = 0.f, s2 = 0.f, s3 = 0.f;
        #pragma unroll
        for (int d = 0; d < 32; ++d) {
            float  kd = kvS[tl * 33 + d];
            float4 rr = v4[d];               // broadcast read
            s0 = fmaf(kd, rr.x, s0);
            s1 = fmaf(kd, rr.y, s1);
            s2 = fmaf(kd, rr.z, s2);
            s3 = fmaf(kd, rr.w, s3);
        }
        if (lane >= T_LEN) { s0 = s1 = s2 = s3 = -1e30f; }

        // ---------- softmax over t (cross-lane butterfly) ----------
        float m0 = s0, m1 = s1, m2 = s2, m3 = s3;
        #pragma unroll
        for (int off = 16; off > 0; off >>= 1) {
            m0 = fmaxf(m0, __shfl_xor_sync(FULL_MASK, m0, off));
            m1 = fmaxf(m1, __shfl_xor_sync(FULL_MASK, m1, off));
            m2 = fmaxf(m2, __shfl_xor_sync(FULL_MASK, m2, off));
            m3 = fmaxf(m3, __shfl_xor_sync(FULL_MASK, m3, off));
        }
        float e0 = (lane < T_LEN) ? __expf(s0 - m0) : 0.f;
        float e1 = (lane < T_LEN) ? __expf(s1 - m1) : 0.f;
        float e2 = (lane < T_LEN) ? __expf(s2 - m2) : 0.f;
        float e3 = (lane < T_LEN) ? __expf(s3 - m3) : 0.f;
        float d0 = e0, d1 = e1, d2 = e2, d3 = e3;
        #pragma unroll
        for (int off = 16; off > 0; off >>= 1) {
            d0 += __shfl_xor_sync(FULL_MASK, d0, off);
            d1 += __shfl_xor_sync(FULL_MASK, d1, off);
            d2 += __shfl_xor_sync(FULL_MASK, d2, off);
            d3 += __shfl_xor_sync(FULL_MASK, d3, off);
        }
        float i0 = __fdividef(1.0f, d0);
        float i1 = __fdividef(1.0f, d1);
        float i2 = __fdividef(1.0f, d2);
        float i3 = __fdividef(1.0f, d3);
        if (lane < T_LEN)
            at4[lane] = make_float4(e0 * i0, e1 * i1, e2 * i2, e3 * i3);
        __syncwarp();

        // ---------- weighted kv: w[h][d] = sum_t attn[h][t] * kv[t][d] ------
        float w0 = 0.f, w1 = 0.f, w2 = 0.f, w3 = 0.f;
        #pragma unroll
        for (int t = 0; t < T_LEN; ++t) {
            float4 at = at4[t];              // broadcast read
            float  kd = kvc[t];              // register column
            w0 = fmaf(at.x, kd, w0);
            w1 = fmaf(at.y, kd, w1);
            w2 = fmaf(at.z, kd, w2);
            w3 = fmaf(at.w, kd, w3);
        }
        // safe to overwrite v4: all lanes passed the at-store __syncwarp
        v4[lane] = make_float4(w0, w1, w2, w3);
        __syncwarp();

        // ---------- ctx[a] = sum_d w[h(a)][d] * Wv[d][a] ----------
        const int h = lane >> 3;
        float ctx = 0.f;
        #pragma unroll
        for (int d = 0; d < 32; ++d)
            ctx = fmaf(v4f[d * 4 + h], sWv[d * 32 + lane], ctx);

        // ---------- out[o] = sum_a ctx[a] * Wo[a][o] ----------
        float o1 = 0.f;
        #pragma unroll
        for (int a = 0; a < 32; ++a)
            o1 = fmaf(__shfl_sync(FULL_MASK, ctx, a), sWo[a * 32 + lane], o1);

        // ---------- LayerNorm over 32 ----------
        float sum = o1;
        #pragma unroll
        for (int off = 16; off > 0; off >>= 1)
            sum += __shfl_xor_sync(FULL_MASK, sum, off);
        float mu = sum * 0.03125f;
        float c  = o1 - mu;
        float vv = c * c;
        #pragma unroll
        for (int off = 16; off > 0; off >>= 1)
            vv += __shfl_xor_sync(FULL_MASK, vv, off);
        float var = vv * 0.03125f;
        float y = c * rsqrtf(var + 1e-5f) * sLn[lane] + sLn[32 + lane];

        // ---------- residual GELU MLP ----------
        float g1 = 0.f;
        #pragma unroll
        for (int o = 0; o < 32; ++o)
            g1 = fmaf(__shfl_sync(FULL_MASK, y, o), sWd1[o * 32 + lane], g1);
        float h1 = gelu_exact(g1);

        float g2 = 0.f;
        #pragma unroll
        for (int o = 0; o < 32; ++o)
            g2 = fmaf(__shfl_sync(FULL_MASK, h1, o), sWd2[o * 32 + lane], g2);
        float h2 = gelu_exact(g2);

        out[row * 32 + lane] = y + h2;
        __syncwarp();   // protect v4/at4/kvS for next iteration
    }
}

extern "C" void kernel_launch(void* const* d_in, const int* in_sizes, int n_in,
                              void* d_out, int out_size)
{
    (void)in_sizes; (void)n_in; (void)out_size;
    const float* query = (const float*)d_in[0];
    const float* kv    = (const float*)d_in[1];
    const float* Wq    = (const float*)d_in[2];
    const float* Wk    = (const float*)d_in[3];
    const float* Wv    = (const float*)d_in[4];
    const float* Wo    = (const float*)d_in[5];
    const float* ln_w  = (const float*)d_in[6];
    const float* ln_b  = (const float*)d_in[7];
    const float* Wd1   = (const float*)d_in[8];
    const float* Wd2   = (const float*)d_in[9];
    float* out = (float*)d_out;

    cross_dmh_attention_kernel<<<NUM_BLOCKS, THREADS_PER_BLOCK>>>(
        query, kv, Wq, Wk, Wv, Wo, ln_w, ln_b, Wd1, Wd2, out);
}

// round 16
// speedup vs baseline: 1.0051x; 1.0049x over previous
#include <cuda_runtime.h>

#define FULL_MASK 0xffffffffu

constexpr int B_TOT = 131072;
constexpr int DQ = 13;
constexpr int DKV = 32;
constexpr int T_LEN = 24;
constexpr int A_DIM = 32;
constexpr int HD = 8;
constexpr int O_DIM = 32;

constexpr int WARPS_PER_BLOCK = 4;
constexpr int THREADS_PER_BLOCK = WARPS_PER_BLOCK * 32;
constexpr int NUM_BLOCKS = 2048;
constexpr int TOTAL_WARPS = NUM_BLOCKS * WARPS_PER_BLOCK;       // 8192
constexpr int ROWS_PER_WARP = B_TOT / TOTAL_WARPS;              // 16

__device__ __forceinline__ float gelu_exact(float x) {
    // jax.nn.gelu(approximate=False): x * 0.5 * (1 + erf(x / sqrt(2)))
    return 0.5f * x * (1.0f + erff(x * 0.70710678118654752f));
}

__global__ __launch_bounds__(THREADS_PER_BLOCK)
void cross_dmh_attention_kernel(const float* __restrict__ query,
                                const float* __restrict__ kv,
                                const float* __restrict__ Wq,
                                const float* __restrict__ Wk,
                                const float* __restrict__ Wv,
                                const float* __restrict__ Wo,
                                const float* __restrict__ ln_w,
                                const float* __restrict__ ln_b,
                                const float* __restrict__ Wd1,
                                const float* __restrict__ Wd2,
                                float* __restrict__ out)
{
    // ---- shared weights (read conflict-free as [k][lane]) ----
    __shared__ float sWq[DQ * 32];       // Wq[j][a], row-major copy
    __shared__ float sWkT[32 * 32];      // sWkT[a][d] = Wk[d][a]   (transposed)
    __shared__ float sWv[32 * 32];       // Wv[d][a], row-major copy
    __shared__ float sWo[32 * 32];       // Wo[a][o], row-major copy
    __shared__ float sWd1[32 * 32];
    __shared__ float sWd2[32 * 32];
    __shared__ float sLn[64];            // [0:32) weight, [32:64) bias
    // ---- per-warp scratch ----
    __shared__ float  sKv[WARPS_PER_BLOCK][T_LEN * 33];   // kv tile, pad 33
    __shared__ float4 sV4[WARPS_PER_BLOCK][32];           // rT then wT: [d] = {v0,v1,v2,v3}
    __shared__ float4 sAt[WARPS_PER_BLOCK][T_LEN];        // attn[t] = {a0,a1,a2,a3}

    const int tid = threadIdx.x;

    for (int i = tid; i < DQ * 32; i += THREADS_PER_BLOCK) sWq[i] = Wq[i];
    for (int i = tid; i < 1024; i += THREADS_PER_BLOCK) {
        int a = i >> 5;        // target row of sWkT
        int d = i & 31;        // target col of sWkT
        sWkT[i] = Wk[d * 32 + a];
        sWv[i]  = Wv[i];
        sWo[i]  = Wo[i];
        sWd1[i] = Wd1[i];
        sWd2[i] = Wd2[i];
    }
    if (tid < 32) { sLn[tid] = ln_w[tid]; sLn[32 + tid] = ln_b[tid]; }
    __syncthreads();

    const int warp = tid >> 5;
    const int lane = tid & 31;
    const int gw   = blockIdx.x * WARPS_PER_BLOCK + warp;

    float*  kvS = sKv[warp];
    float4* v4  = sV4[warp];
    float*  v4f = (float*)sV4[warp];
    float4* at4 = sAt[warp];

    for (int it = 0; it < ROWS_PER_WARP; ++it) {
        const int row = gw + it * TOTAL_WARPS;

        // ---------- q projection: q[a] = sum_j query[j] * Wq[j][a] ----------
        float qv = (lane < DQ) ? query[row * DQ + lane] : 0.0f;
        float qa = 0.0f;
        #pragma unroll
        for (int j = 0; j < DQ; ++j)
            qa = fmaf(__shfl_sync(FULL_MASK, qv, j), sWq[j * 32 + lane], qa);

        // ---------- r[h][d] = sum_{j<8} Wk[d][h*8+j] * q[h*8+j], scaled ------
        float r0 = 0.f, r1 = 0.f, r2 = 0.f, r3 = 0.f;
        #pragma unroll
        for (int j = 0; j < HD; ++j) {
            r0 = fmaf(__shfl_sync(FULL_MASK, qa, j),      sWkT[(j)      * 32 + lane], r0);
            r1 = fmaf(__shfl_sync(FULL_MASK, qa, 8 + j),  sWkT[(8 + j)  * 32 + lane], r1);
            r2 = fmaf(__shfl_sync(FULL_MASK, qa, 16 + j), sWkT[(16 + j) * 32 + lane], r2);
            r3 = fmaf(__shfl_sync(FULL_MASK, qa, 24 + j), sWkT[(24 + j) * 32 + lane], r3);
        }
        const float iscale = 0.35355339059327373f;   // 1/sqrt(8)
        v4[lane] = make_float4(r0 * iscale, r1 * iscale, r2 * iscale, r3 * iscale);

        // ---------- kv tile: coalesced load, keep column in regs + stage ----
        float kvc[T_LEN];
        const float* kvrow = kv + (size_t)row * (T_LEN * DKV);
        #pragma unroll
        for (int t = 0; t < T_LEN; ++t) {
            float v = kvrow[t * 32 + lane];
            kvc[t] = v;
            kvS[t * 33 + lane] = v;
        }
        __syncwarp();

        // ---------- scores: lane = t, s[h] = kv[t] . r[h] ----------
        const int tl = (lane < T_LEN) ? lane : 0;
        float s0 = 0.f, s1 = 0.f, s2 = 0.f, s3 = 0.f;
        #pragma unroll
        for (int d = 0; d < 32; ++d) {
            float  kd = kvS[tl * 33 + d];
            float4 rr = v4[d];               // broadcast read
            s0 = fmaf(kd, rr.x, s0);
            s1 = fmaf(kd, rr.y, s1);
            s2 = fmaf(kd, rr.z, s2);
            s3 = fmaf(kd, rr.w, s3);
        }
        if (lane >= T_LEN) { s0 = s1 = s2 = s3 = -1e30f; }

        // ---------- softmax over t (cross-lane butterfly) ----------
        float m0 = s0, m1 = s1, m2 = s2, m3 = s3;
        #pragma unroll
        for (int off = 16; off > 0; off >>= 1) {
            m0 = fmaxf(m0, __shfl_xor_sync(FULL_MASK, m0, off));
            m1 = fmaxf(m1, __shfl_xor_sync(FULL_MASK, m1, off));
            m2 = fmaxf(m2, __shfl_xor_sync(FULL_MASK, m2, off));
            m3 = fmaxf(m3, __shfl_xor_sync(FULL_MASK, m3, off));
        }
        float e0 = (lane < T_LEN) ? __expf(s0 - m0) : 0.f;
        float e1 = (lane < T_LEN) ? __expf(s1 - m1) : 0.f;
        float e2 = (lane < T_LEN) ? __expf(s2 - m2) : 0.f;
        float e3 = (lane < T_LEN) ? __expf(s3 - m3) : 0.f;
        float d0 = e0, d1 = e1, d2 = e2, d3 = e3;
        #pragma unroll
        for (int off = 16; off > 0; off >>= 1) {
            d0 += __shfl_xor_sync(FULL_MASK, d0, off);
            d1 += __shfl_xor_sync(FULL_MASK, d1, off);
            d2 += __shfl_xor_sync(FULL_MASK, d2, off);
            d3 += __shfl_xor_sync(FULL_MASK, d3, off);
        }
        float i0 = __fdividef(1.0f, d0);
        float i1 = __fdividef(1.0f, d1);
        float i2 = __fdividef(1.0f, d2);
        float i3 = __fdividef(1.0f, d3);
        if (lane < T_LEN)
            at4[lane] = make_float4(e0 * i0, e1 * i1, e2 * i2, e3 * i3);
        __syncwarp();

        // ---------- weighted kv: w[h][d] = sum_t attn[h][t] * kv[t][d] ------
        float w0 = 0.f, w1 = 0.f, w2 = 0.f, w3 = 0.f;
        #pragma unroll
        for (int t = 0; t < T_LEN; ++t) {
            float4 at = at4[t];              // broadcast read
            float  kd = kvc[t];              // register column
            w0 = fmaf(at.x, kd, w0);
            w1 = fmaf(at.y, kd, w1);
            w2 = fmaf(at.z, kd, w2);
            w3 = fmaf(at.w, kd, w3);
        }
        // safe to overwrite v4: all lanes passed the at-store __syncwarp
        v4[lane] = make_float4(w0, w1, w2, w3);
        __syncwarp();

        // ---------- ctx[a] = sum_d w[h(a)][d] * Wv[d][a] ----------
        const int h = lane >> 3;
        float ctx = 0.f;
        #pragma unroll
        for (int d = 0; d < 32; ++d)
            ctx = fmaf(v4f[d * 4 + h], sWv[d * 32 + lane], ctx);

        // ---------- out[o] = sum_a ctx[a] * Wo[a][o] ----------
        float o1 = 0.f;
        #pragma unroll
        for (int a = 0; a < 32; ++a)
            o1 = fmaf(__shfl_sync(FULL_MASK, ctx, a), sWo[a * 32 + lane], o1);

        // ---------- LayerNorm over 32 ----------
        float sum = o1;
        #pragma unroll
        for (int off = 16; off > 0; off >>= 1)
            sum += __shfl_xor_sync(FULL_MASK, sum, off);
        float mu = sum * 0.03125f;
        float c  = o1 - mu;
        float vv = c * c;
        #pragma unroll
        for (int off = 16; off > 0; off >>= 1)
            vv += __shfl_xor_sync(FULL_MASK, vv, off);
        float var = vv * 0.03125f;
        float y = c * rsqrtf(var + 1e-5f) * sLn[lane] + sLn[32 + lane];

        // ---------- residual GELU MLP ----------
        float g1 = 0.f;
        #pragma unroll
        for (int o = 0; o < 32; ++o)
            g1 = fmaf(__shfl_sync(FULL_MASK, y, o), sWd1[o * 32 + lane], g1);
        float h1 = gelu_exact(g1);

        float g2 = 0.f;
        #pragma unroll
        for (int o = 0; o < 32; ++o)
            g2 = fmaf(__shfl_sync(FULL_MASK, h1, o), sWd2[o * 32 + lane], g2);
        float h2 = gelu_exact(g2);

        out[row * 32 + lane] = y + h2;
        __syncwarp();   // protect v4/at4/kvS for next iteration
    }
}

extern "C" void kernel_launch(void* const* d_in, const int* in_sizes, int n_in,
                              void* d_out, int out_size)
{
    (void)in_sizes; (void)n_in; (void)out_size;
    const float* query = (const float*)d_in[0];
    const float* kv    = (const float*)d_in[1];
    const float* Wq    = (const float*)d_in[2];
    const float* Wk    = (const float*)d_in[3];
    const float* Wv    = (const float*)d_in[4];
    const float* Wo    = (const float*)d_in[5];
    const float* ln_w  = (const float*)d_in[6];
    const float* ln_b  = (const float*)d_in[7];
    const float* Wd1   = (const float*)d_in[8];
    const float* Wd2   = (const float*)d_in[9];
    float* out = (float*)d_out;

    cross_dmh_attention_kernel<<<NUM_BLOCKS, THREADS_PER_BLOCK>>>(
        query, kv, Wq, Wk, Wv, Wo, ln_w, ln_b, Wd1, Wd2, out);
}

// round 17
// speedup vs baseline: 1.0055x; 1.0004x over previous
#include <cuda_runtime.h>

#define FULL_MASK 0xffffffffu

constexpr int B_TOT = 131072;
constexpr int DQ = 13;
constexpr int DKV = 32;
constexpr int T_LEN = 24;
constexpr int A_DIM = 32;
constexpr int HD = 8;
constexpr int O_DIM = 32;

constexpr int WARPS_PER_BLOCK = 4;
constexpr int THREADS_PER_BLOCK = WARPS_PER_BLOCK * 32;
constexpr int NUM_BLOCKS = 2048;
constexpr int TOTAL_WARPS = NUM_BLOCKS * WARPS_PER_BLOCK;       // 8192
constexpr int ROWS_PER_WARP = B_TOT / TOTAL_WARPS;              // 16

__device__ __forceinline__ float gelu_exact(float x) {
    // jax.nn.gelu(approximate=False): x * 0.5 * (1 + erf(x / sqrt(2)))
    return 0.5f * x * (1.0f + erff(x * 0.70710678118654752f));
}

__global__ __launch_bounds__(THREADS_PER_BLOCK)
void cross_dmh_attention_kernel(const float* __restrict__ query,
                                const float* __restrict__ kv,
                                const float* __restrict__ Wq,
                                const float* __restrict__ Wk,
                                const float* __restrict__ Wv,
                                const float* __restrict__ Wo,
                                const float* __restrict__ ln_w,
                                const float* __restrict__ ln_b,
                                const float* __restrict__ Wd1,
                                const float* __restrict__ Wd2,
                                float* __restrict__ out)
{
    // ---- shared weights (read conflict-free as [k][lane]) ----
    __shared__ float sWq[DQ * 32];       // Wq[j][a], row-major copy
    __shared__ float sWkT[32 * 32];      // sWkT[a][d] = Wk[d][a]   (transposed)
    __shared__ float sWv[32 * 32];       // Wv[d][a], row-major copy
    __shared__ float sWo[32 * 32];       // Wo[a][o], row-major copy
    __shared__ float sWd1[32 * 32];
    __shared__ float sWd2[32 * 32];
    __shared__ float sLn[64];            // [0:32) weight, [32:64) bias
    // ---- per-warp scratch ----
    __shared__ float  sKv[WARPS_PER_BLOCK][T_LEN * 33];   // kv tile, pad 33
    __shared__ float4 sV4[WARPS_PER_BLOCK][32];           // rT then wT: [d] = {v0,v1,v2,v3}
    __shared__ float4 sAt[WARPS_PER_BLOCK][T_LEN];        // attn[t] = {a0,a1,a2,a3}

    const int tid = threadIdx.x;

    for (int i = tid; i < DQ * 32; i += THREADS_PER_BLOCK) sWq[i] = Wq[i];
    for (int i = tid; i < 1024; i += THREADS_PER_BLOCK) {
        int a = i >> 5;        // target row of sWkT
        int d = i & 31;        // target col of sWkT
        sWkT[i] = Wk[d * 32 + a];
        sWv[i]  = Wv[i];
        sWo[i]  = Wo[i];
        sWd1[i] = Wd1[i];
        sWd2[i] = Wd2[i];
    }
    if (tid < 32) { sLn[tid] = ln_w[tid]; sLn[32 + tid] = ln_b[tid]; }
    __syncthreads();

    const int warp = tid >> 5;
    const int lane = tid & 31;
    const int gw   = blockIdx.x * WARPS_PER_BLOCK + warp;

    float*  kvS = sKv[warp];
    float4* v4  = sV4[warp];
    float*  v4f = (float*)sV4[warp];
    float4* at4 = sAt[warp];

    for (int it = 0; it < ROWS_PER_WARP; ++it) {
        const int row = gw + it * TOTAL_WARPS;

        // ---------- q projection: q[a] = sum_j query[j] * Wq[j][a] ----------
        float qv = (lane < DQ) ? query[row * DQ + lane] : 0.0f;
        float qa = 0.0f;
        #pragma unroll
        for (int j = 0; j < DQ; ++j)
            qa = fmaf(__shfl_sync(FULL_MASK, qv, j), sWq[j * 32 + lane], qa);

        // ---------- r[h][d] = sum_{j<8} Wk[d][h*8+j] * q[h*8+j], scaled ------
        float r0 = 0.f, r1 = 0.f, r2 = 0.f, r3 = 0.f;
        #pragma unroll
        for (int j = 0; j < HD; ++j) {
            r0 = fmaf(__shfl_sync(FULL_MASK, qa, j),      sWkT[(j)      * 32 + lane], r0);
            r1 = fmaf(__shfl_sync(FULL_MASK, qa, 8 + j),  sWkT[(8 + j)  * 32 + lane], r1);
            r2 = fmaf(__shfl_sync(FULL_MASK, qa, 16 + j), sWkT[(16 + j) * 32 + lane], r2);
            r3 = fmaf(__shfl_sync(FULL_MASK, qa, 24 + j), sWkT[(24 + j) * 32 + lane], r3);
        }
        const float iscale = 0.35355339059327373f;   // 1/sqrt(8)
        v4[lane] = make_float4(r0 * iscale, r1 * iscale, r2 * iscale, r3 * iscale);

        // ---------- kv tile: coalesced load, keep column in regs + stage ----
        float kvc[T_LEN];
        const float* kvrow = kv + (size_t)row * (T_LEN * DKV);
        #pragma unroll
        for (int t = 0; t < T_LEN; ++t) {
            float v = kvrow[t * 32 + lane];
            kvc[t] = v;
            kvS[t * 33 + lane] = v;
        }
        __syncwarp();

        // ---------- scores: lane = t, s[h] = kv[t] . r[h] ----------
        const int tl = (lane < T_LEN) ? lane : 0;
        float s0 = 0.f, s1 = 0.f, s2 = 0.f, s3 = 0.f;
        #pragma unroll
        for (int d = 0; d < 32; ++d) {
            float  kd = kvS[tl * 33 + d];
            float4 rr = v4[d];               // broadcast read
            s0 = fmaf(kd, rr.x, s0);
            s1 = fmaf(kd, rr.y, s1);
            s2 = fmaf(kd, rr.z, s2);
            s3 = fmaf(kd, rr.w, s3);
        }
        if (lane >= T_LEN) { s0 = s1 = s2 = s3 = -1e30f; }

        // ---------- softmax over t (cross-lane butterfly) ----------
        float m0 = s0, m1 = s1, m2 = s2, m3 = s3;
        #pragma unroll
        for (int off = 16; off > 0; off >>= 1) {
            m0 = fmaxf(m0, __shfl_xor_sync(FULL_MASK, m0, off));
            m1 = fmaxf(m1, __shfl_xor_sync(FULL_MASK, m1, off));
            m2 = fmaxf(m2, __shfl_xor_sync(FULL_MASK, m2, off));
            m3 = fmaxf(m3, __shfl_xor_sync(FULL_MASK, m3, off));
        }
        float e0 = (lane < T_LEN) ? __expf(s0 - m0) : 0.f;
        float e1 = (lane < T_LEN) ? __expf(s1 - m1) : 0.f;
        float e2 = (lane < T_LEN) ? __expf(s2 - m2) : 0.f;
        float e3 = (lane < T_LEN) ? __expf(s3 - m3) : 0.f;
        float d0 = e0, d1 = e1, d2 = e2, d3 = e3;
        #pragma unroll
        for (int off = 16; off > 0; off >>= 1) {
            d0 += __shfl_xor_sync(FULL_MASK, d0, off);
            d1 += __shfl_xor_sync(FULL_MASK, d1, off);
            d2 += __shfl_xor_sync(FULL_MASK, d2, off);
            d3 += __shfl_xor_sync(FULL_MASK, d3, off);
        }
        float i0 = __fdividef(1.0f, d0);
        float i1 = __fdividef(1.0f, d1);
        float i2 = __fdividef(1.0f, d2);
        float i3 = __fdividef(1.0f, d3);
        if (lane < T_LEN)
            at4[lane] = make_float4(e0 * i0, e1 * i1, e2 * i2, e3 * i3);
        __syncwarp();

        // ---------- weighted kv: w[h][d] = sum_t attn[h][t] * kv[t][d] ------
        float w0 = 0.f, w1 = 0.f, w2 = 0.f, w3 = 0.f;
        #pragma unroll
        for (int t = 0; t < T_LEN; ++t) {
            float4 at = at4[t];              // broadcast read
            float  kd = kvc[t];              // register column
            w0 = fmaf(at.x, kd, w0);
            w1 = fmaf(at.y, kd, w1);
            w2 = fmaf(at.z, kd, w2);
            w3 = fmaf(at.w, kd, w3);
        }
        // safe to overwrite v4: all lanes passed the at-store __syncwarp
        v4[lane] = make_float4(w0, w1, w2, w3);
        __syncwarp();

        // ---------- ctx[a] = sum_d w[h(a)][d] * Wv[d][a] ----------
        const int h = lane >> 3;
        float ctx = 0.f;
        #pragma unroll
        for (int d = 0; d < 32; ++d)
            ctx = fmaf(v4f[d * 4 + h], sWv[d * 32 + lane], ctx);

        // ---------- out[o] = sum_a ctx[a] * Wo[a][o] ----------
        float o1 = 0.f;
        #pragma unroll
        for (int a = 0; a < 32; ++a)
            o1 = fmaf(__shfl_sync(FULL_MASK, ctx, a), sWo[a * 32 + lane], o1);

        // ---------- LayerNorm over 32 ----------
        float sum = o1;
        #pragma unroll
        for (int off = 16; off > 0; off >>= 1)
            sum += __shfl_xor_sync(FULL_MASK, sum, off);
        float mu = sum * 0.03125f;
        float c  = o1 - mu;
        float vv = c * c;
        #pragma unroll
        for (int off = 16; off > 0; off >>= 1)
            vv += __shfl_xor_sync(FULL_MASK, vv, off);
        float var = vv * 0.03125f;
        float y = c * rsqrtf(var + 1e-5f) * sLn[lane] + sLn[32 + lane];

        // ---------- residual GELU MLP ----------
        float g1 = 0.f;
        #pragma unroll
        for (int o = 0; o < 32; ++o)
            g1 = fmaf(__shfl_sync(FULL_MASK, y, o), sWd1[o * 32 + lane], g1);
        float h1 = gelu_exact(g1);

        float g2 = 0.f;
        #pragma unroll
        for (int o = 0; o < 32; ++o)
            g2 = fmaf(__shfl_sync(FULL_MASK, h1, o), sWd2[o * 32 + lane], g2);
        float h2 = gelu_exact(g2);

        out[row * 32 + lane] = y + h2;
        __syncwarp();   // protect v4/at4/kvS for next iteration
    }
}

extern "C" void kernel_launch(void* const* d_in, const int* in_sizes, int n_in,
                              void* d_out, int out_size)
{
    (void)in_sizes; (void)n_in; (void)out_size;
    const float* query = (const float*)d_in[0];
    const float* kv    = (const float*)d_in[1];
    const float* Wq    = (const float*)d_in[2];
    const float* Wk    = (const float*)d_in[3];
    const float* Wv    = (const float*)d_in[4];
    const float* Wo    = (const float*)d_in[5];
    const float* ln_w  = (const float*)d_in[6];
    const float* ln_b  = (const float*)d_in[7];
    const float* Wd1   = (const float*)d_in[8];
    const float* Wd2   = (const float*)d_in[9];
    float* out = (float*)d_out;

    cross_dmh_attention_kernel<<<NUM_BLOCKS, THREADS_PER_BLOCK>>>(
        query, kv, Wq, Wk, Wv, Wo, ln_w, ln_b, Wd1, Wd2, out);
}